// round 13
// baseline (speedup 1.0000x reference)
#include <cuda_runtime.h>
#include <cstdint>

#define HID 128
#define NB 50000
#define NC 2500
#define NLAYERS 2
#define NBF (NB*HID)
#define NCF (NC*HID)

typedef unsigned long long u64;

#define SA_STRIDE 132
#define TROWS 32                                   // tile rows (double-buffered)
#define SMEM_BYTES ((HID*HID + 2*TROWS*SA_STRIDE)*4)  // 64K + 2x16.9K = 99328 -> 2 CTAs/SM
#define GRID_P 296

#define FLAG_GELU 1
#define FLAG_EDGE 2

// ---------- packed f32x2 helpers ----------
__device__ __forceinline__ u64 pack2(float x, float y){
    u64 d; asm("mov.b64 %0, {%1, %2};" : "=l"(d) : "f"(x), "f"(y)); return d;
}
__device__ __forceinline__ float2 unpack2(u64 d){
    float2 v; asm("mov.b64 {%0, %1}, %2;" : "=f"(v.x), "=f"(v.y) : "l"(d)); return v;
}
__device__ __forceinline__ u64 fma2(u64 a, u64 b, u64 c){
    u64 d; asm("fma.rn.f32x2 %0, %1, %2, %3;" : "=l"(d) : "l"(a), "l"(b), "l"(c)); return d;
}
// ---------- branchless erf, A&S 7.1.26 ----------
__device__ __forceinline__ float erf_apx(float z){   // z >= 0
    float den = fmaf(0.3275911f, z, 1.0f);
    float t; asm("rcp.approx.f32 %0, %1;" : "=f"(t) : "f"(den));
    float p = fmaf(1.061405429f, t, -1.453152027f);
    p = fmaf(p, t, 1.421413741f);
    p = fmaf(p, t, -0.284496736f);
    p = fmaf(p, t, 0.254829592f);
    p = p * t;
    float e = __expf(-z * z);
    return fmaf(-p, e, 1.0f);
}
__device__ __forceinline__ float gelu_f(float x){
    float z = fabsf(x) * 0.70710678118654752440f;
    float er = copysignf(erf_apx(z), x);
    return 0.5f * x * (1.0f + er);
}
__device__ __forceinline__ float gelu_w(float x, float hw){   // hw = 0.5*w
    float z = fabsf(x) * 0.70710678118654752440f;
    float er = copysignf(erf_apx(z), x);
    return hw * x * (1.0f + er);
}
__device__ __forceinline__ void red_add_v4(float* p, float a, float b, float c, float d){
    asm volatile("red.global.add.v4.f32 [%0], {%1, %2, %3, %4};"
                 :: "l"(p), "f"(a), "f"(b), "f"(c), "f"(d) : "memory");
}
__device__ __forceinline__ void prefetch_l1(const void* p){
    asm volatile("prefetch.global.L1 [%0];" :: "l"(p));
}
__device__ __forceinline__ uint32_t smem_u32(const void* p){
    uint32_t a; asm("{ .reg .u64 t; cvta.to.shared.u64 t, %1; cvt.u32.u64 %0, t; }" : "=r"(a) : "l"(p));
    return a;
}
__device__ __forceinline__ void cp_async16(uint32_t daddr, const void* src){
    asm volatile("cp.async.cg.shared.global [%0], [%1], 16;" :: "r"(daddr), "l"(src));
}

// ---------- job table ----------
struct Job {
    const float* A; const float* W; const float* bias;
    float* out;
    const int* ei; const float* ew; const float* xs;
    const float* eps;
    int rows; int tile_ofs; int flags; int _pad;
};
struct JobTab { Job j[8]; int njobs; int total_tiles; };

__device__ __forceinline__ int job_of(const JobTab& tab, int tile){
    int jid = 0;
    #pragma unroll
    for (int q = 1; q < 8; q++)
        if (q < tab.njobs && tile >= tab.j[q].tile_ofs) jid = q;
    return jid;
}

// stage tile's 32x128 A panel into buf via cp.async (zeros OOB rows via STS)
__device__ __forceinline__ void stage_tile(const JobTab& tab, int tile, float* buf,
                                           uint32_t bufaddr, int t){
    int jid = job_of(tab, tile);
    const Job& J = tab.j[jid];
    int row0 = (tile - J.tile_ofs) * TROWS;
    const float4* A4 = (const float4*)J.A;
    #pragma unroll
    for (int i = 0; i < 4; i++){
        int idx = t + 256*i;
        int r = idx >> 5, c4 = idx & 31;
        if (row0 + r < J.rows)
            cp_async16(bufaddr + (uint32_t)(r*SA_STRIDE + 4*c4)*4,
                       A4 + (size_t)(row0 + r)*32 + c4);
        else
            *reinterpret_cast<float4*>(buf + r*SA_STRIDE + 4*c4) = make_float4(0.f,0.f,0.f,0.f);
    }
    asm volatile("cp.async.commit_group;" ::: "memory");
}

// ---------- persistent multi-job fused GEMM kernel ----------
// Tile 32 rows x 128 cols. thread t: tr=t/16 -> rows 2tr,2tr+1; tc=t%16 -> cols {4tc..+3, 4tc+64..+67}
extern "C" __global__ void __launch_bounds__(256, 2)
mega_gemm(JobTab tab)
{
    extern __shared__ float smem[];
    float* sW  = smem;                          // [k][c] 128x128, eps-scale folded
    float* sA0 = smem + HID*HID;
    float* sA1 = sA0 + TROWS*SA_STRIDE;
    uint32_t a0addr = smem_u32(sA0);
    uint32_t a1addr = smem_u32(sA1);
    int t = threadIdx.x;
    int tr = t >> 4, tc = t & 15;
    int cached = -1;
    int pb = 0;

    int tile = blockIdx.x;
    if (tile < tab.total_tiles) stage_tile(tab, tile, sA0, a0addr, t);

    for (; tile < tab.total_tiles; tile += gridDim.x){
        int jid = job_of(tab, tile);
        const Job J = tab.j[jid];
        int row0 = (tile - J.tile_ofs) * TROWS;

        if (jid != cached){
            __syncthreads();         // all warps done with old sW (and prior epilogues)
            float scale = J.eps ? (1.0f + *J.eps) : 1.0f;
            const float4* W4 = (const float4*)J.W;
            float4* s4 = (float4*)sW;
            #pragma unroll
            for (int i = 0; i < 16; i++){
                float4 v = W4[t + 256*i];
                v.x *= scale; v.y *= scale; v.z *= scale; v.w *= scale;
                s4[t + 256*i] = v;
            }
            cached = jid;
        }

        asm volatile("cp.async.wait_group 0;" ::: "memory");   // current tile's panel landed
        __syncthreads();             // all staging visible; prev iter's reads closed

        // issue next tile's staging into the other buffer (overlaps this mainloop)
        int nxt = tile + (int)gridDim.x;
        if (nxt < tab.total_tiles)
            stage_tile(tab, nxt, pb ? sA0 : sA1, pb ? a0addr : a1addr, t);

        const float* sA = pb ? sA1 : sA0;

        // ---- edge metadata + xs prefetch ----
        int2 s2 = make_int2(0,0);
        if (J.flags & FLAG_EDGE){
            s2 = *reinterpret_cast<const int2*>(J.ei + row0 + 2*tr);   // E%32==0
            if (tc < 4){
                prefetch_l1(J.xs + (size_t)s2.x*HID + tc*32);
                prefetch_l1(J.xs + (size_t)s2.y*HID + tc*32);
            }
        }

        // ---- mainloop: 2 rows x 8 cols per thread ----
        u64 acc[2][2][2];
        #pragma unroll
        for (int r=0;r<2;r++)
            #pragma unroll
            for (int j=0;j<2;j++){ acc[r][j][0]=0ULL; acc[r][j][1]=0ULL; }

        const float* aRow0 = sA + (2*tr)*SA_STRIDE;
        const float* aRow1 = aRow0 + SA_STRIDE;
        #pragma unroll 2
        for (int k0 = 0; k0 < HID; k0 += 4){
            float4 a0 = *reinterpret_cast<const float4*>(aRow0 + k0);
            float4 a1 = *reinterpret_cast<const float4*>(aRow1 + k0);
            #pragma unroll
            for (int kk=0;kk<4;kk++){
                const float* wrow = sW + (k0+kk)*HID + 4*tc;
                ulonglong2 w0 = *reinterpret_cast<const ulonglong2*>(wrow);
                ulonglong2 w1 = *reinterpret_cast<const ulonglong2*>(wrow + 64);
                float av0 = (kk==0)?a0.x:(kk==1)?a0.y:(kk==2)?a0.z:a0.w;
                float av1 = (kk==0)?a1.x:(kk==1)?a1.y:(kk==2)?a1.z:a1.w;
                u64 p0 = pack2(av0, av0), p1 = pack2(av1, av1);
                acc[0][0][0] = fma2(p0, w0.x, acc[0][0][0]);
                acc[0][0][1] = fma2(p0, w0.y, acc[0][0][1]);
                acc[0][1][0] = fma2(p0, w1.x, acc[0][1][0]);
                acc[0][1][1] = fma2(p0, w1.y, acc[0][1][1]);
                acc[1][0][0] = fma2(p1, w0.x, acc[1][0][0]);
                acc[1][0][1] = fma2(p1, w0.y, acc[1][0][1]);
                acc[1][1][0] = fma2(p1, w1.x, acc[1][1][0]);
                acc[1][1][1] = fma2(p1, w1.y, acc[1][1][1]);
            }
        }

        // ---- fused epilogue ----
        float4 bv0 = *reinterpret_cast<const float4*>(J.bias + 4*tc);
        float4 bv1 = *reinterpret_cast<const float4*>(J.bias + 4*tc + 64);
        if (!(J.flags & FLAG_EDGE)){
            #pragma unroll
            for (int r=0;r<2;r++){
                int row = row0 + 2*tr + r;
                if (row >= J.rows) continue;
                float2 a00 = unpack2(acc[r][0][0]);
                float2 a01 = unpack2(acc[r][0][1]);
                float2 a10 = unpack2(acc[r][1][0]);
                float2 a11 = unpack2(acc[r][1][1]);
                float o0 = a00.x + bv0.x, o1 = a00.y + bv0.y;
                float o2 = a01.x + bv0.z, o3 = a01.y + bv0.w;
                float p0 = a10.x + bv1.x, p1 = a10.y + bv1.y;
                float p2 = a11.x + bv1.z, p3 = a11.y + bv1.w;
                if (J.flags & FLAG_GELU){
                    o0=gelu_f(o0); o1=gelu_f(o1); o2=gelu_f(o2); o3=gelu_f(o3);
                    p0=gelu_f(p0); p1=gelu_f(p1); p2=gelu_f(p2); p3=gelu_f(p3);
                }
                *reinterpret_cast<float4*>(J.out + (size_t)row*HID + 4*tc)      = make_float4(o0,o1,o2,o3);
                *reinterpret_cast<float4*>(J.out + (size_t)row*HID + 4*tc + 64) = make_float4(p0,p1,p2,p3);
            }
        } else {
            int2   d2 = *reinterpret_cast<const int2*>(J.ei + J.rows + row0 + 2*tr);
            float2 w2 = *reinterpret_cast<const float2*>(J.ew + row0 + 2*tr);
            int   srcs[2] = {s2.x, s2.y};
            int   dsts[2] = {d2.x, d2.y};
            float hwts[2] = {0.5f*w2.x, 0.5f*w2.y};
            #pragma unroll
            for (int r=0;r<2;r++){
                const float* xsr = J.xs + (size_t)srcs[r]*HID;
                float4 xv0 = *reinterpret_cast<const float4*>(xsr + 4*tc);
                float4 xv1 = *reinterpret_cast<const float4*>(xsr + 4*tc + 64);
                float2 a00 = unpack2(acc[r][0][0]);
                float2 a01 = unpack2(acc[r][0][1]);
                float2 a10 = unpack2(acc[r][1][0]);
                float2 a11 = unpack2(acc[r][1][1]);
                float hw = hwts[r];
                float m0 = gelu_w(a00.x + bv0.x + xv0.x, hw);
                float m1 = gelu_w(a00.y + bv0.y + xv0.y, hw);
                float m2 = gelu_w(a01.x + bv0.z + xv0.z, hw);
                float m3 = gelu_w(a01.y + bv0.w + xv0.w, hw);
                float n0 = gelu_w(a10.x + bv1.x + xv1.x, hw);
                float n1 = gelu_w(a10.y + bv1.y + xv1.y, hw);
                float n2 = gelu_w(a11.x + bv1.z + xv1.z, hw);
                float n3 = gelu_w(a11.y + bv1.w + xv1.w, hw);
                float* op = J.out + (size_t)dsts[r]*HID + 4*tc;
                red_add_v4(op,      m0, m1, m2, m3);
                red_add_v4(op + 64, n0, n1, n2, n3);
            }
        }
        pb ^= 1;
    }
}

// ---------- x += gelu(a + b) ----------
extern "C" __global__ void combine_kernel(float* __restrict__ x, const float* __restrict__ a,
                                          const float* __restrict__ b, int n){
    int i = blockIdx.x * blockDim.x + threadIdx.x;
    if (i < n) x[i] += gelu_f(a[i] + b[i]);
}

// ---------- scratch ----------
__device__ float g_buf[(size_t)5*NBF + (size_t)5*NCF];

static void addJob(JobTab& T, const float* A, const float* W, const float* b, float* out,
                   int rows, const float* eps, int flags,
                   const int* ei = nullptr, const float* ew = nullptr, const float* xs = nullptr){
    Job& J = T.j[T.njobs];
    J.A = A; J.W = W; J.bias = b; J.out = out;
    J.ei = ei; J.ew = ew; J.xs = xs; J.eps = eps;
    J.rows = rows; J.tile_ofs = T.total_tiles; J.flags = flags; J._pad = 0;
    T.total_tiles += (rows + TROWS - 1) / TROWS;
    T.njobs++;
}
static void launch_tab(const JobTab& T){
    int G = T.total_tiles < GRID_P ? T.total_tiles : GRID_P;
    mega_gemm<<<G, 256, SMEM_BYTES>>>(T);
}

extern "C" void kernel_launch(void* const* d_in, const int* in_sizes, int n_in,
                              void* d_out, int out_size)
{
    (void)n_in; (void)out_size;
    const float* x_base = (const float*)d_in[0];
    const float* x_cent = (const float*)d_in[1];
    const int*   ei[4]  = {(const int*)d_in[2], (const int*)d_in[5], (const int*)d_in[8],  (const int*)d_in[11]};
    const float* ea[4]  = {(const float*)d_in[3], (const float*)d_in[6], (const float*)d_in[9],  (const float*)d_in[12]};
    const float* ewt[4] = {(const float*)d_in[4], (const float*)d_in[7], (const float*)d_in[10], (const float*)d_in[13]};
    const float* Wsrc = (const float*)d_in[14];
    const float* bsrc = (const float*)d_in[15];
    const float* Wdst = (const float*)d_in[16];
    const float* bdst = (const float*)d_in[17];
    const float* eps  = (const float*)d_in[18];
    const float* We   = (const float*)d_in[19];
    const float* be   = (const float*)d_in[20];
    const float* Wm1  = (const float*)d_in[21];
    const float* bm1  = (const float*)d_in[22];
    const float* Wm2  = (const float*)d_in[23];
    const float* bm2  = (const float*)d_in[24];

    float* base = nullptr;
    cudaGetSymbolAddress((void**)&base, g_buf);
    float* xb     = base;
    float* xs_bb  = base + (size_t)1*NBF;
    float* xs_bc  = base + (size_t)2*NBF;
    float* agg_bb = base + (size_t)3*NBF;
    float* agg_cb = base + (size_t)4*NBF;
    float* xc     = base + (size_t)5*NBF;
    float* xs_cc  = xc + (size_t)1*NCF;
    float* xs_cb  = xc + (size_t)2*NCF;
    float* agg_bc = xc + (size_t)3*NCF;
    float* agg_cc = xc + (size_t)4*NCF;

    cudaFuncSetAttribute((const void*)mega_gemm, cudaFuncAttributeMaxDynamicSharedMemorySize, SMEM_BYTES);

    cudaMemcpyAsync(xb, x_base, sizeof(float)*(size_t)NBF, cudaMemcpyDeviceToDevice, 0);
    cudaMemcpyAsync(xc, x_cent, sizeof(float)*(size_t)NCF, cudaMemcpyDeviceToDevice, 0);

    for (int l = 0; l < NLAYERS; l++){
        #define WOFF(P,t) ((P) + ((size_t)l*4 + (t))*HID*HID)
        #define BOFF(P,t) ((P) + ((size_t)l*4 + (t))*HID)
        // NODE8: 4x lin_src + 4x lin_dst
        {
            JobTab T = {};
            addJob(T, xb, WOFF(Wsrc,0), BOFF(bsrc,0), xs_bb, NB, nullptr, 0);
            addJob(T, xb, WOFF(Wsrc,1), BOFF(bsrc,1), xs_bc, NB, nullptr, 0);
            addJob(T, xc, WOFF(Wsrc,2), BOFF(bsrc,2), xs_cc, NC, nullptr, 0);
            addJob(T, xc, WOFF(Wsrc,3), BOFF(bsrc,3), xs_cb, NC, nullptr, 0);
            addJob(T, xb, WOFF(Wdst,0), BOFF(bdst,0), agg_bb, NB, eps + l*4 + 0, 0);
            addJob(T, xb, WOFF(Wdst,3), BOFF(bdst,3), agg_cb, NB, eps + l*4 + 3, 0);
            addJob(T, xc, WOFF(Wdst,1), BOFF(bdst,1), agg_bc, NC, eps + l*4 + 1, 0);
            addJob(T, xc, WOFF(Wdst,2), BOFF(bdst,2), agg_cc, NC, eps + l*4 + 2, 0);
            launch_tab(T);
        }
        // EDGE4
        {
            const float* XSs[4]  = {xs_bb, xs_bc, xs_cc, xs_cb};
            float*       AGGs[4] = {agg_bb, agg_bc, agg_cc, agg_cb};
            JobTab T = {};
            for (int tt = 0; tt < 4; tt++){
                int E = in_sizes[4 + 3*tt];
                addJob(T, ea[tt], WOFF(We,tt), BOFF(be,tt), AGGs[tt], E, nullptr, FLAG_EDGE,
                       ei[tt], ewt[tt], XSs[tt]);
            }
            launch_tab(T);
        }
        // MLP1 (gelu)
        {
            JobTab T = {};
            addJob(T, agg_bb, WOFF(Wm1,0), BOFF(bm1,0), xs_bb, NB, nullptr, FLAG_GELU);
            addJob(T, agg_cb, WOFF(Wm1,3), BOFF(bm1,3), xs_bc, NB, nullptr, FLAG_GELU);
            addJob(T, agg_bc, WOFF(Wm1,1), BOFF(bm1,1), xs_cc, NC, nullptr, FLAG_GELU);
            addJob(T, agg_cc, WOFF(Wm1,2), BOFF(bm1,2), xs_cb, NC, nullptr, FLAG_GELU);
            launch_tab(T);
        }
        // MLP2
        {
            JobTab T = {};
            addJob(T, xs_bb, WOFF(Wm2,0), BOFF(bm2,0), agg_bb, NB, nullptr, 0);
            addJob(T, xs_bc, WOFF(Wm2,3), BOFF(bm2,3), agg_cb, NB, nullptr, 0);
            addJob(T, xs_cc, WOFF(Wm2,1), BOFF(bm2,1), agg_bc, NC, nullptr, 0);
            addJob(T, xs_cb, WOFF(Wm2,2), BOFF(bm2,2), agg_cc, NC, nullptr, 0);
            launch_tab(T);
        }
        // residual + gelu combine
        combine_kernel<<<(NBF+255)/256, 256>>>(xb, agg_bb, agg_cb, NBF);
        combine_kernel<<<(NCF+255)/256, 256>>>(xc, agg_bc, agg_cc, NCF);
        #undef WOFF
        #undef BOFF
    }

    float* out = (float*)d_out;
    cudaMemcpyAsync(out,       xb, sizeof(float)*(size_t)NBF, cudaMemcpyDeviceToDevice, 0);
    cudaMemcpyAsync(out + NBF, xc, sizeof(float)*(size_t)NCF, cudaMemcpyDeviceToDevice, 0);
}

// round 14
// speedup vs baseline: 1.4239x; 1.4239x over previous
#include <cuda_runtime.h>
#include <cstdint>

#define HID 128
#define NB 50000
#define NC 2500
#define NLAYERS 2
#define NBF (NB*HID)
#define NCF (NC*HID)

typedef unsigned long long u64;

#define SA_STRIDE 132
#define SMEM_BYTES ((HID*HID + 64*SA_STRIDE)*4)   // 99328 B -> 2 CTAs/SM
#define GRID_P 296

#define FLAG_GELU 1
#define FLAG_EDGE 2

// ---------- packed f32x2 helpers ----------
__device__ __forceinline__ u64 pack2(float x, float y){
    u64 d; asm("mov.b64 %0, {%1, %2};" : "=l"(d) : "f"(x), "f"(y)); return d;
}
__device__ __forceinline__ float2 unpack2(u64 d){
    float2 v; asm("mov.b64 {%0, %1}, %2;" : "=f"(v.x), "=f"(v.y) : "l"(d)); return v;
}
__device__ __forceinline__ u64 fma2(u64 a, u64 b, u64 c){
    u64 d; asm("fma.rn.f32x2 %0, %1, %2, %3;" : "=l"(d) : "l"(a), "l"(b), "l"(c)); return d;
}
// ---------- branchless erf, A&S 7.1.26 ----------
__device__ __forceinline__ float erf_apx(float z){   // z >= 0
    float den = fmaf(0.3275911f, z, 1.0f);
    float t; asm("rcp.approx.f32 %0, %1;" : "=f"(t) : "f"(den));
    float p = fmaf(1.061405429f, t, -1.453152027f);
    p = fmaf(p, t, 1.421413741f);
    p = fmaf(p, t, -0.284496736f);
    p = fmaf(p, t, 0.254829592f);
    p = p * t;
    float e = __expf(-z * z);
    return fmaf(-p, e, 1.0f);
}
__device__ __forceinline__ float gelu_f(float x){
    float z = fabsf(x) * 0.70710678118654752440f;
    float er = copysignf(erf_apx(z), x);
    return 0.5f * x * (1.0f + er);
}
__device__ __forceinline__ float gelu_w(float x, float hw){   // hw = 0.5*w
    float z = fabsf(x) * 0.70710678118654752440f;
    float er = copysignf(erf_apx(z), x);
    return hw * x * (1.0f + er);
}
__device__ __forceinline__ void red_add_v4(float* p, float a, float b, float c, float d){
    asm volatile("red.global.add.v4.f32 [%0], {%1, %2, %3, %4};"
                 :: "l"(p), "f"(a), "f"(b), "f"(c), "f"(d) : "memory");
}
__device__ __forceinline__ void prefetch_l1(const void* p){
    asm volatile("prefetch.global.L1 [%0];" :: "l"(p));
}
// streaming (evict-first) float4 load — keeps L2 for xs/agg working set
__device__ __forceinline__ float4 ldcs4(const float4* p){
    float4 v;
    asm volatile("ld.global.cs.v4.f32 {%0,%1,%2,%3}, [%4];"
                 : "=f"(v.x), "=f"(v.y), "=f"(v.z), "=f"(v.w) : "l"(p));
    return v;
}

// ---------- job table ----------
struct Job {
    const float* A; const float* W; const float* bias;
    float* out;
    const int* ei; const float* ew; const float* xs;
    const float* eps;
    int rows; int tile_ofs; int flags; int _pad;
};
struct JobTab { Job j[8]; int njobs; int total_tiles; };

// ---------- persistent multi-job fused GEMM kernel ----------
// Tile 64x128. thread t: tr=t/16 -> rows 4tr..+3, tc=t%16 -> cols {4tc..+3, 4tc+64..+67}
extern "C" __global__ void __launch_bounds__(256, 2)
mega_gemm(JobTab tab)
{
    extern __shared__ float smem[];
    float* sW = smem;                 // [k][c] 128x128, eps-scale folded
    float* sA = smem + HID*HID;       // 64 x SA_STRIDE
    int t = threadIdx.x;
    int tr = t >> 4, tc = t & 15, r0 = tr * 4;
    int cached = -1;

    for (int tile = blockIdx.x; tile < tab.total_tiles; tile += gridDim.x){
        int jid = 0;
        #pragma unroll
        for (int q = 1; q < 8; q++)
            if (q < tab.njobs && tile >= tab.j[q].tile_ofs) jid = q;
        const Job J = tab.j[jid];
        int row0 = (tile - J.tile_ofs) * 64;

        __syncthreads();   // previous iteration done reading smem
        if (jid != cached){
            float scale = J.eps ? (1.0f + *J.eps) : 1.0f;
            const float4* W4 = (const float4*)J.W;
            float4* s4 = (float4*)sW;
            #pragma unroll
            for (int i = 0; i < 16; i++){
                float4 v = W4[t + 256*i];
                v.x *= scale; v.y *= scale; v.z *= scale; v.w *= scale;
                s4[t + 256*i] = v;
            }
            cached = jid;
        }
        // ---- stage A: batch 8 LDG (MLP=8) then 8 STS ----
        // Edge jobs: ea is read-once -> streaming .cs loads (don't pollute L2;
        // xs gather targets + agg RED targets stay L2-resident).
        {
            const float4* A4 = (const float4*)J.A;
            bool strm = (J.flags & FLAG_EDGE) != 0;
            float4 v[8];
            #pragma unroll
            for (int i = 0; i < 8; i++){
                int idx = t + 256*i;
                int r = idx >> 5, c4 = idx & 31;
                if (row0 + r < J.rows){
                    const float4* p = A4 + (size_t)(row0 + r)*32 + c4;
                    v[i] = strm ? ldcs4(p) : *p;
                } else {
                    v[i] = make_float4(0.f,0.f,0.f,0.f);
                }
            }
            #pragma unroll
            for (int i = 0; i < 8; i++){
                int idx = t + 256*i;
                int r = idx >> 5, c4 = idx & 31;
                *reinterpret_cast<float4*>(sA + r*SA_STRIDE + 4*c4) = v[i];
            }
        }
        // ---- edge: load src rows, prefetch xs gather lines (L1) ----
        int4 src4 = make_int4(0,0,0,0);
        if (J.flags & FLAG_EDGE){
            src4 = *reinterpret_cast<const int4*>(J.ei + row0 + r0);   // E % 64 == 0: no guard
            if (tc < 4){
                prefetch_l1(J.xs + (size_t)src4.x*HID + tc*32);
                prefetch_l1(J.xs + (size_t)src4.y*HID + tc*32);
                prefetch_l1(J.xs + (size_t)src4.z*HID + tc*32);
                prefetch_l1(J.xs + (size_t)src4.w*HID + tc*32);
            }
        }
        // ---- prefetch next tile's A panel (1 line/thread = full 32KB) ----
        {
            int nrow = row0 + (int)gridDim.x*64 + (t >> 2);
            if (nrow < J.rows)
                prefetch_l1(J.A + (size_t)nrow*HID + (t & 3)*32);
        }
        __syncthreads();

        // ---- mainloop (FFMA2 peak) ----
        u64 acc[4][2][2];
        #pragma unroll
        for (int r=0;r<4;r++)
            #pragma unroll
            for (int j=0;j<2;j++){ acc[r][j][0]=0ULL; acc[r][j][1]=0ULL; }
        #pragma unroll 2
        for (int k0 = 0; k0 < HID; k0 += 4){
            float4 av[4];
            #pragma unroll
            for (int r=0;r<4;r++)
                av[r] = *reinterpret_cast<const float4*>(sA + (r0+r)*SA_STRIDE + k0);
            #pragma unroll
            for (int kk=0;kk<4;kk++){
                const float* wrow = sW + (k0+kk)*HID + 4*tc;
                ulonglong2 w0 = *reinterpret_cast<const ulonglong2*>(wrow);
                ulonglong2 w1 = *reinterpret_cast<const ulonglong2*>(wrow + 64);
                #pragma unroll
                for (int r=0;r<4;r++){
                    float a = (kk==0)?av[r].x:(kk==1)?av[r].y:(kk==2)?av[r].z:av[r].w;
                    u64 a2 = pack2(a, a);
                    acc[r][0][0] = fma2(a2, w0.x, acc[r][0][0]);
                    acc[r][0][1] = fma2(a2, w0.y, acc[r][0][1]);
                    acc[r][1][0] = fma2(a2, w1.x, acc[r][1][0]);
                    acc[r][1][1] = fma2(a2, w1.y, acc[r][1][1]);
                }
            }
        }

        // ---- fused epilogue ----
        float4 bv0 = *reinterpret_cast<const float4*>(J.bias + 4*tc);
        float4 bv1 = *reinterpret_cast<const float4*>(J.bias + 4*tc + 64);
        if (!(J.flags & FLAG_EDGE)){
            #pragma unroll
            for (int r=0;r<4;r++){
                int row = row0 + r0 + r;
                if (row >= J.rows) continue;
                float2 a00 = unpack2(acc[r][0][0]);
                float2 a01 = unpack2(acc[r][0][1]);
                float2 a10 = unpack2(acc[r][1][0]);
                float2 a11 = unpack2(acc[r][1][1]);
                float o0 = a00.x + bv0.x, o1 = a00.y + bv0.y;
                float o2 = a01.x + bv0.z, o3 = a01.y + bv0.w;
                float p0 = a10.x + bv1.x, p1 = a10.y + bv1.y;
                float p2 = a11.x + bv1.z, p3 = a11.y + bv1.w;
                if (J.flags & FLAG_GELU){
                    o0=gelu_f(o0); o1=gelu_f(o1); o2=gelu_f(o2); o3=gelu_f(o3);
                    p0=gelu_f(p0); p1=gelu_f(p1); p2=gelu_f(p2); p3=gelu_f(p3);
                }
                *reinterpret_cast<float4*>(J.out + (size_t)row*HID + 4*tc)      = make_float4(o0,o1,o2,o3);
                *reinterpret_cast<float4*>(J.out + (size_t)row*HID + 4*tc + 64) = make_float4(p0,p1,p2,p3);
            }
        } else {
            int4   dst4 = *reinterpret_cast<const int4*>(J.ei + J.rows + row0 + r0);
            float4 ew4  = *reinterpret_cast<const float4*>(J.ew + row0 + r0);
            int   srcs[4] = {src4.x, src4.y, src4.z, src4.w};
            int   dsts[4] = {dst4.x, dst4.y, dst4.z, dst4.w};
            float hwts[4] = {0.5f*ew4.x, 0.5f*ew4.y, 0.5f*ew4.z, 0.5f*ew4.w};
            #pragma unroll
            for (int r=0;r<4;r++){
                const float* xsr = J.xs + (size_t)srcs[r]*HID;
                float4 xv0 = *reinterpret_cast<const float4*>(xsr + 4*tc);
                float4 xv1 = *reinterpret_cast<const float4*>(xsr + 4*tc + 64);
                float2 a00 = unpack2(acc[r][0][0]);
                float2 a01 = unpack2(acc[r][0][1]);
                float2 a10 = unpack2(acc[r][1][0]);
                float2 a11 = unpack2(acc[r][1][1]);
                float hw = hwts[r];
                float m0 = gelu_w(a00.x + bv0.x + xv0.x, hw);
                float m1 = gelu_w(a00.y + bv0.y + xv0.y, hw);
                float m2 = gelu_w(a01.x + bv0.z + xv0.z, hw);
                float m3 = gelu_w(a01.y + bv0.w + xv0.w, hw);
                float n0 = gelu_w(a10.x + bv1.x + xv1.x, hw);
                float n1 = gelu_w(a10.y + bv1.y + xv1.y, hw);
                float n2 = gelu_w(a11.x + bv1.z + xv1.z, hw);
                float n3 = gelu_w(a11.y + bv1.w + xv1.w, hw);
                float* op = J.out + (size_t)dsts[r]*HID + 4*tc;
                red_add_v4(op,      m0, m1, m2, m3);
                red_add_v4(op + 64, n0, n1, n2, n3);
            }
        }
    }
}

// ---------- x += gelu(a + b) ----------
extern "C" __global__ void combine_kernel(float* __restrict__ x, const float* __restrict__ a,
                                          const float* __restrict__ b, int n){
    int i = blockIdx.x * blockDim.x + threadIdx.x;
    if (i < n) x[i] += gelu_f(a[i] + b[i]);
}

// ---------- scratch ----------
__device__ float g_buf[(size_t)5*NBF + (size_t)5*NCF];

static void addJob(JobTab& T, const float* A, const float* W, const float* b, float* out,
                   int rows, const float* eps, int flags,
                   const int* ei = nullptr, const float* ew = nullptr, const float* xs = nullptr){
    Job& J = T.j[T.njobs];
    J.A = A; J.W = W; J.bias = b; J.out = out;
    J.ei = ei; J.ew = ew; J.xs = xs; J.eps = eps;
    J.rows = rows; J.tile_ofs = T.total_tiles; J.flags = flags; J._pad = 0;
    T.total_tiles += (rows + 63) / 64;
    T.njobs++;
}
static void launch_tab(const JobTab& T){
    int G = T.total_tiles < GRID_P ? T.total_tiles : GRID_P;
    mega_gemm<<<G, 256, SMEM_BYTES>>>(T);
}

extern "C" void kernel_launch(void* const* d_in, const int* in_sizes, int n_in,
                              void* d_out, int out_size)
{
    (void)n_in; (void)out_size;
    const float* x_base = (const float*)d_in[0];
    const float* x_cent = (const float*)d_in[1];
    const int*   ei[4]  = {(const int*)d_in[2], (const int*)d_in[5], (const int*)d_in[8],  (const int*)d_in[11]};
    const float* ea[4]  = {(const float*)d_in[3], (const float*)d_in[6], (const float*)d_in[9],  (const float*)d_in[12]};
    const float* ewt[4] = {(const float*)d_in[4], (const float*)d_in[7], (const float*)d_in[10], (const float*)d_in[13]};
    const float* Wsrc = (const float*)d_in[14];
    const float* bsrc = (const float*)d_in[15];
    const float* Wdst = (const float*)d_in[16];
    const float* bdst = (const float*)d_in[17];
    const float* eps  = (const float*)d_in[18];
    const float* We   = (const float*)d_in[19];
    const float* be   = (const float*)d_in[20];
    const float* Wm1  = (const float*)d_in[21];
    const float* bm1  = (const float*)d_in[22];
    const float* Wm2  = (const float*)d_in[23];
    const float* bm2  = (const float*)d_in[24];

    float* base = nullptr;
    cudaGetSymbolAddress((void**)&base, g_buf);
    float* xb     = base;
    float* xs_bb  = base + (size_t)1*NBF;
    float* xs_bc  = base + (size_t)2*NBF;
    float* agg_bb = base + (size_t)3*NBF;
    float* agg_cb = base + (size_t)4*NBF;
    float* xc     = base + (size_t)5*NBF;
    float* xs_cc  = xc + (size_t)1*NCF;
    float* xs_cb  = xc + (size_t)2*NCF;
    float* agg_bc = xc + (size_t)3*NCF;
    float* agg_cc = xc + (size_t)4*NCF;

    cudaFuncSetAttribute((const void*)mega_gemm, cudaFuncAttributeMaxDynamicSharedMemorySize, SMEM_BYTES);

    cudaMemcpyAsync(xb, x_base, sizeof(float)*(size_t)NBF, cudaMemcpyDeviceToDevice, 0);
    cudaMemcpyAsync(xc, x_cent, sizeof(float)*(size_t)NCF, cudaMemcpyDeviceToDevice, 0);

    for (int l = 0; l < NLAYERS; l++){
        #define WOFF(P,t) ((P) + ((size_t)l*4 + (t))*HID*HID)
        #define BOFF(P,t) ((P) + ((size_t)l*4 + (t))*HID)
        // NODE8: 4x lin_src + 4x lin_dst
        {
            JobTab T = {};
            addJob(T, xb, WOFF(Wsrc,0), BOFF(bsrc,0), xs_bb, NB, nullptr, 0);
            addJob(T, xb, WOFF(Wsrc,1), BOFF(bsrc,1), xs_bc, NB, nullptr, 0);
            addJob(T, xc, WOFF(Wsrc,2), BOFF(bsrc,2), xs_cc, NC, nullptr, 0);
            addJob(T, xc, WOFF(Wsrc,3), BOFF(bsrc,3), xs_cb, NC, nullptr, 0);
            addJob(T, xb, WOFF(Wdst,0), BOFF(bdst,0), agg_bb, NB, eps + l*4 + 0, 0);
            addJob(T, xb, WOFF(Wdst,3), BOFF(bdst,3), agg_cb, NB, eps + l*4 + 3, 0);
            addJob(T, xc, WOFF(Wdst,1), BOFF(bdst,1), agg_bc, NC, eps + l*4 + 1, 0);
            addJob(T, xc, WOFF(Wdst,2), BOFF(bdst,2), agg_cc, NC, eps + l*4 + 2, 0);
            launch_tab(T);
        }
        // EDGE4
        {
            const float* XSs[4]  = {xs_bb, xs_bc, xs_cc, xs_cb};
            float*       AGGs[4] = {agg_bb, agg_bc, agg_cc, agg_cb};
            JobTab T = {};
            for (int tt = 0; tt < 4; tt++){
                int E = in_sizes[4 + 3*tt];
                addJob(T, ea[tt], WOFF(We,tt), BOFF(be,tt), AGGs[tt], E, nullptr, FLAG_EDGE,
                       ei[tt], ewt[tt], XSs[tt]);
            }
            launch_tab(T);
        }
        // MLP1 (gelu)
        {
            JobTab T = {};
            addJob(T, agg_bb, WOFF(Wm1,0), BOFF(bm1,0), xs_bb, NB, nullptr, FLAG_GELU);
            addJob(T, agg_cb, WOFF(Wm1,3), BOFF(bm1,3), xs_bc, NB, nullptr, FLAG_GELU);
            addJob(T, agg_bc, WOFF(Wm1,1), BOFF(bm1,1), xs_cc, NC, nullptr, FLAG_GELU);
            addJob(T, agg_cc, WOFF(Wm1,2), BOFF(bm1,2), xs_cb, NC, nullptr, FLAG_GELU);
            launch_tab(T);
        }
        // MLP2
        {
            JobTab T = {};
            addJob(T, xs_bb, WOFF(Wm2,0), BOFF(bm2,0), agg_bb, NB, nullptr, 0);
            addJob(T, xs_bc, WOFF(Wm2,3), BOFF(bm2,3), agg_cb, NB, nullptr, 0);
            addJob(T, xs_cc, WOFF(Wm2,1), BOFF(bm2,1), agg_bc, NC, nullptr, 0);
            addJob(T, xs_cb, WOFF(Wm2,2), BOFF(bm2,2), agg_cc, NC, nullptr, 0);
            launch_tab(T);
        }
        // residual + gelu combine
        combine_kernel<<<(NBF+255)/256, 256>>>(xb, agg_bb, agg_cb, NBF);
        combine_kernel<<<(NCF+255)/256, 256>>>(xc, agg_bc, agg_cc, NCF);
        #undef WOFF
        #undef BOFF
    }

    float* out = (float*)d_out;
    cudaMemcpyAsync(out,       xb, sizeof(float)*(size_t)NBF, cudaMemcpyDeviceToDevice, 0);
    cudaMemcpyAsync(out + NBF, xc, sizeof(float)*(size_t)NCF, cudaMemcpyDeviceToDevice, 0);
}

// round 15
// speedup vs baseline: 1.4757x; 1.0364x over previous
#include <cuda_runtime.h>
#include <cstdint>

#define HID 128
#define NB 50000
#define NC 2500
#define NLAYERS 2
#define NBF (NB*HID)
#define NCF (NC*HID)

typedef unsigned long long u64;

#define SA_STRIDE 132
#define SMEM_BYTES ((HID*HID + 64*SA_STRIDE)*4)   // 99328 B -> 2 CTAs/SM
#define GRID_P 296

#define FLAG_GELU 1
#define FLAG_EDGE 2

// ---------- packed f32x2 helpers ----------
__device__ __forceinline__ u64 pack2(float x, float y){
    u64 d; asm("mov.b64 %0, {%1, %2};" : "=l"(d) : "f"(x), "f"(y)); return d;
}
__device__ __forceinline__ float2 unpack2(u64 d){
    float2 v; asm("mov.b64 {%0, %1}, %2;" : "=f"(v.x), "=f"(v.y) : "l"(d)); return v;
}
__device__ __forceinline__ u64 fma2(u64 a, u64 b, u64 c){
    u64 d; asm("fma.rn.f32x2 %0, %1, %2, %3;" : "=l"(d) : "l"(a), "l"(b), "l"(c)); return d;
}
// ---------- branchless erf, A&S 7.1.26 ----------
__device__ __forceinline__ float erf_apx(float z){   // z >= 0
    float den = fmaf(0.3275911f, z, 1.0f);
    float t; asm("rcp.approx.f32 %0, %1;" : "=f"(t) : "f"(den));
    float p = fmaf(1.061405429f, t, -1.453152027f);
    p = fmaf(p, t, 1.421413741f);
    p = fmaf(p, t, -0.284496736f);
    p = fmaf(p, t, 0.254829592f);
    p = p * t;
    float e = __expf(-z * z);
    return fmaf(-p, e, 1.0f);
}
__device__ __forceinline__ float gelu_f(float x){
    float z = fabsf(x) * 0.70710678118654752440f;
    float er = copysignf(erf_apx(z), x);
    return 0.5f * x * (1.0f + er);
}
__device__ __forceinline__ float gelu_w(float x, float hw){   // hw = 0.5*w
    float z = fabsf(x) * 0.70710678118654752440f;
    float er = copysignf(erf_apx(z), x);
    return hw * x * (1.0f + er);
}
__device__ __forceinline__ void red_add_v4(float* p, float a, float b, float c, float d){
    asm volatile("red.global.add.v4.f32 [%0], {%1, %2, %3, %4};"
                 :: "l"(p), "f"(a), "f"(b), "f"(c), "f"(d) : "memory");
}
__device__ __forceinline__ void prefetch_l1(const void* p){
    asm volatile("prefetch.global.L1 [%0];" :: "l"(p));
}

// ---------- job table ----------
struct Job {
    const float* A; const float* W; const float* bias;
    float* out;
    const int* ei; const float* ew; const float* xs;
    const float* eps;
    int rows; int tile_ofs; int flags; int _pad;
};
struct JobTab { Job j[8]; int njobs; int total_tiles; };

// ---------- persistent multi-job fused GEMM kernel ----------
// Tile 64x128. thread t: tr=t/16 -> rows 4tr..+3, tc=t%16 -> cols {4tc..+3, 4tc+64..+67}
// Warp w's mainloop consumes only sA rows 8w..8w+7.
extern "C" __global__ void __launch_bounds__(256, 2)
mega_gemm(JobTab tab)
{
    extern __shared__ float smem[];
    float* sW = smem;                 // [k][c] 128x128, eps-scale folded
    float* sA = smem + HID*HID;       // 64 x SA_STRIDE
    int t = threadIdx.x;
    int tr = t >> 4, tc = t & 15, r0 = tr * 4;
    int w = t >> 5, l = t & 31;
    int cached = -1;

    for (int tile = blockIdx.x; tile < tab.total_tiles; tile += gridDim.x){
        int jid = 0;
        #pragma unroll
        for (int q = 1; q < 8; q++)
            if (q < tab.njobs && tile >= tab.j[q].tile_ofs) jid = q;
        const Job J = tab.j[jid];
        int row0 = (tile - J.tile_ofs) * 64;
        const bool edge = (J.flags & FLAG_EDGE) != 0;

        if (jid != cached){
            __syncthreads();          // all warps done with old sW/sA
            float scale = J.eps ? (1.0f + *J.eps) : 1.0f;
            const float4* W4 = (const float4*)J.W;
            float4* s4 = (float4*)sW;
            #pragma unroll
            for (int i = 0; i < 16; i++){
                float4 v = W4[t + 256*i];
                v.x *= scale; v.y *= scale; v.z *= scale; v.w *= scale;
                s4[t + 256*i] = v;
            }
            cached = jid;
            __syncthreads();
        }

        int4 src4 = make_int4(0,0,0,0);
        if (!edge){
            // ======== NODE staging: CTA-wide, barriered (proven at peak) ========
            __syncthreads();          // previous tile's sA reads done
            {
                const float4* A4 = (const float4*)J.A;
                float4 v[8];
                #pragma unroll
                for (int i = 0; i < 8; i++){
                    int idx = t + 256*i;
                    int r = idx >> 5, c4 = idx & 31;
                    v[i] = (row0 + r < J.rows) ? A4[(size_t)(row0 + r)*32 + c4]
                                               : make_float4(0.f,0.f,0.f,0.f);
                }
                #pragma unroll
                for (int i = 0; i < 8; i++){
                    int idx = t + 256*i;
                    int r = idx >> 5, c4 = idx & 31;
                    *reinterpret_cast<float4*>(sA + r*SA_STRIDE + 4*c4) = v[i];
                }
            }
            // prefetch next tile's A panel (1 line/thread = full 32KB)
            {
                int nrow = row0 + (int)gridDim.x*64 + (t >> 2);
                if (nrow < J.rows)
                    prefetch_l1(J.A + (size_t)nrow*HID + (t & 3)*32);
            }
            __syncthreads();
        } else {
            // ======== EDGE staging: per-warp private (rows 8w..8w+7), NO CTA barrier ====
            src4 = *reinterpret_cast<const int4*>(J.ei + row0 + r0);   // E%64==0
            if (tc < 4){   // prefetch xs gather lines early
                prefetch_l1(J.xs + (size_t)src4.x*HID + tc*32);
                prefetch_l1(J.xs + (size_t)src4.y*HID + tc*32);
                prefetch_l1(J.xs + (size_t)src4.z*HID + tc*32);
                prefetch_l1(J.xs + (size_t)src4.w*HID + tc*32);
            }
            {
                const float4* A4 = (const float4*)J.A;
                int rr = 8*w + (l >> 2);           // this lane's row
                int cq = l & 3;
                const float4* gp = A4 + (size_t)(row0 + rr)*32 + cq;
                float4 v[8];
                #pragma unroll
                for (int i = 0; i < 8; i++) v[i] = gp[4*i];
                float* sp = sA + rr*SA_STRIDE + 4*cq;
                #pragma unroll
                for (int i = 0; i < 8; i++)
                    *reinterpret_cast<float4*>(sp + 16*i) = v[i];
            }
            // per-warp prefetch of next tile's own rows
            {
                int nt0 = row0 + (int)gridDim.x*64;
                if (nt0 < J.rows)
                    prefetch_l1(J.A + (size_t)(nt0 + 8*w + (l >> 2))*HID + (l & 3)*32);
            }
            __syncwarp();
        }

        // ---- mainloop (FFMA2 peak) ----
        u64 acc[4][2][2];
        #pragma unroll
        for (int r=0;r<4;r++)
            #pragma unroll
            for (int j=0;j<2;j++){ acc[r][j][0]=0ULL; acc[r][j][1]=0ULL; }
        #pragma unroll 2
        for (int k0 = 0; k0 < HID; k0 += 4){
            float4 av[4];
            #pragma unroll
            for (int r=0;r<4;r++)
                av[r] = *reinterpret_cast<const float4*>(sA + (r0+r)*SA_STRIDE + k0);
            #pragma unroll
            for (int kk=0;kk<4;kk++){
                const float* wrow = sW + (k0+kk)*HID + 4*tc;
                ulonglong2 w0 = *reinterpret_cast<const ulonglong2*>(wrow);
                ulonglong2 w1 = *reinterpret_cast<const ulonglong2*>(wrow + 64);
                #pragma unroll
                for (int r=0;r<4;r++){
                    float a = (kk==0)?av[r].x:(kk==1)?av[r].y:(kk==2)?av[r].z:av[r].w;
                    u64 a2 = pack2(a, a);
                    acc[r][0][0] = fma2(a2, w0.x, acc[r][0][0]);
                    acc[r][0][1] = fma2(a2, w0.y, acc[r][0][1]);
                    acc[r][1][0] = fma2(a2, w1.x, acc[r][1][0]);
                    acc[r][1][1] = fma2(a2, w1.y, acc[r][1][1]);
                }
            }
        }

        // ---- fused epilogue ----
        float4 bv0 = *reinterpret_cast<const float4*>(J.bias + 4*tc);
        float4 bv1 = *reinterpret_cast<const float4*>(J.bias + 4*tc + 64);
        if (!edge){
            #pragma unroll
            for (int r=0;r<4;r++){
                int row = row0 + r0 + r;
                if (row >= J.rows) continue;
                float2 a00 = unpack2(acc[r][0][0]);
                float2 a01 = unpack2(acc[r][0][1]);
                float2 a10 = unpack2(acc[r][1][0]);
                float2 a11 = unpack2(acc[r][1][1]);
                float o0 = a00.x + bv0.x, o1 = a00.y + bv0.y;
                float o2 = a01.x + bv0.z, o3 = a01.y + bv0.w;
                float p0 = a10.x + bv1.x, p1 = a10.y + bv1.y;
                float p2 = a11.x + bv1.z, p3 = a11.y + bv1.w;
                if (J.flags & FLAG_GELU){
                    o0=gelu_f(o0); o1=gelu_f(o1); o2=gelu_f(o2); o3=gelu_f(o3);
                    p0=gelu_f(p0); p1=gelu_f(p1); p2=gelu_f(p2); p3=gelu_f(p3);
                }
                *reinterpret_cast<float4*>(J.out + (size_t)row*HID + 4*tc)      = make_float4(o0,o1,o2,o3);
                *reinterpret_cast<float4*>(J.out + (size_t)row*HID + 4*tc + 64) = make_float4(p0,p1,p2,p3);
            }
        } else {
            int4   dst4 = *reinterpret_cast<const int4*>(J.ei + J.rows + row0 + r0);
            float4 ew4  = *reinterpret_cast<const float4*>(J.ew + row0 + r0);
            int   srcs[4] = {src4.x, src4.y, src4.z, src4.w};
            int   dsts[4] = {dst4.x, dst4.y, dst4.z, dst4.w};
            float hwts[4] = {0.5f*ew4.x, 0.5f*ew4.y, 0.5f*ew4.z, 0.5f*ew4.w};
            #pragma unroll
            for (int r=0;r<4;r++){
                const float* xsr = J.xs + (size_t)srcs[r]*HID;
                float4 xv0 = *reinterpret_cast<const float4*>(xsr + 4*tc);
                float4 xv1 = *reinterpret_cast<const float4*>(xsr + 4*tc + 64);
                float2 a00 = unpack2(acc[r][0][0]);
                float2 a01 = unpack2(acc[r][0][1]);
                float2 a10 = unpack2(acc[r][1][0]);
                float2 a11 = unpack2(acc[r][1][1]);
                float hw = hwts[r];
                float m0 = gelu_w(a00.x + bv0.x + xv0.x, hw);
                float m1 = gelu_w(a00.y + bv0.y + xv0.y, hw);
                float m2 = gelu_w(a01.x + bv0.z + xv0.z, hw);
                float m3 = gelu_w(a01.y + bv0.w + xv0.w, hw);
                float n0 = gelu_w(a10.x + bv1.x + xv1.x, hw);
                float n1 = gelu_w(a10.y + bv1.y + xv1.y, hw);
                float n2 = gelu_w(a11.x + bv1.z + xv1.z, hw);
                float n3 = gelu_w(a11.y + bv1.w + xv1.w, hw);
                float* op = J.out + (size_t)dsts[r]*HID + 4*tc;
                red_add_v4(op,      m0, m1, m2, m3);
                red_add_v4(op + 64, n0, n1, n2, n3);
            }
        }
    }
}

// ---------- x += gelu(a + b) ----------
extern "C" __global__ void combine_kernel(float* __restrict__ x, const float* __restrict__ a,
                                          const float* __restrict__ b, int n){
    int i = blockIdx.x * blockDim.x + threadIdx.x;
    if (i < n) x[i] += gelu_f(a[i] + b[i]);
}

// ---------- scratch ----------
__device__ float g_buf[(size_t)5*NBF + (size_t)5*NCF];

static void addJob(JobTab& T, const float* A, const float* W, const float* b, float* out,
                   int rows, const float* eps, int flags,
                   const int* ei = nullptr, const float* ew = nullptr, const float* xs = nullptr){
    Job& J = T.j[T.njobs];
    J.A = A; J.W = W; J.bias = b; J.out = out;
    J.ei = ei; J.ew = ew; J.xs = xs; J.eps = eps;
    J.rows = rows; J.tile_ofs = T.total_tiles; J.flags = flags; J._pad = 0;
    T.total_tiles += (rows + 63) / 64;
    T.njobs++;
}
static void launch_tab(const JobTab& T){
    int G = T.total_tiles < GRID_P ? T.total_tiles : GRID_P;
    mega_gemm<<<G, 256, SMEM_BYTES>>>(T);
}

extern "C" void kernel_launch(void* const* d_in, const int* in_sizes, int n_in,
                              void* d_out, int out_size)
{
    (void)n_in; (void)out_size;
    const float* x_base = (const float*)d_in[0];
    const float* x_cent = (const float*)d_in[1];
    const int*   ei[4]  = {(const int*)d_in[2], (const int*)d_in[5], (const int*)d_in[8],  (const int*)d_in[11]};
    const float* ea[4]  = {(const float*)d_in[3], (const float*)d_in[6], (const float*)d_in[9],  (const float*)d_in[12]};
    const float* ewt[4] = {(const float*)d_in[4], (const float*)d_in[7], (const float*)d_in[10], (const float*)d_in[13]};
    const float* Wsrc = (const float*)d_in[14];
    const float* bsrc = (const float*)d_in[15];
    const float* Wdst = (const float*)d_in[16];
    const float* bdst = (const float*)d_in[17];
    const float* eps  = (const float*)d_in[18];
    const float* We   = (const float*)d_in[19];
    const float* be   = (const float*)d_in[20];
    const float* Wm1  = (const float*)d_in[21];
    const float* bm1  = (const float*)d_in[22];
    const float* Wm2  = (const float*)d_in[23];
    const float* bm2  = (const float*)d_in[24];

    float* base = nullptr;
    cudaGetSymbolAddress((void**)&base, g_buf);
    float* xb     = base;
    float* xs_bb  = base + (size_t)1*NBF;
    float* xs_bc  = base + (size_t)2*NBF;
    float* agg_bb = base + (size_t)3*NBF;
    float* agg_cb = base + (size_t)4*NBF;
    float* xc     = base + (size_t)5*NBF;
    float* xs_cc  = xc + (size_t)1*NCF;
    float* xs_cb  = xc + (size_t)2*NCF;
    float* agg_bc = xc + (size_t)3*NCF;
    float* agg_cc = xc + (size_t)4*NCF;

    cudaFuncSetAttribute((const void*)mega_gemm, cudaFuncAttributeMaxDynamicSharedMemorySize, SMEM_BYTES);

    cudaMemcpyAsync(xb, x_base, sizeof(float)*(size_t)NBF, cudaMemcpyDeviceToDevice, 0);
    cudaMemcpyAsync(xc, x_cent, sizeof(float)*(size_t)NCF, cudaMemcpyDeviceToDevice, 0);

    for (int l = 0; l < NLAYERS; l++){
        #define WOFF(P,t) ((P) + ((size_t)l*4 + (t))*HID*HID)
        #define BOFF(P,t) ((P) + ((size_t)l*4 + (t))*HID)
        // NODE8: 4x lin_src + 4x lin_dst
        {
            JobTab T = {};
            addJob(T, xb, WOFF(Wsrc,0), BOFF(bsrc,0), xs_bb, NB, nullptr, 0);
            addJob(T, xb, WOFF(Wsrc,1), BOFF(bsrc,1), xs_bc, NB, nullptr, 0);
            addJob(T, xc, WOFF(Wsrc,2), BOFF(bsrc,2), xs_cc, NC, nullptr, 0);
            addJob(T, xc, WOFF(Wsrc,3), BOFF(bsrc,3), xs_cb, NC, nullptr, 0);
            addJob(T, xb, WOFF(Wdst,0), BOFF(bdst,0), agg_bb, NB, eps + l*4 + 0, 0);
            addJob(T, xb, WOFF(Wdst,3), BOFF(bdst,3), agg_cb, NB, eps + l*4 + 3, 0);
            addJob(T, xc, WOFF(Wdst,1), BOFF(bdst,1), agg_bc, NC, eps + l*4 + 1, 0);
            addJob(T, xc, WOFF(Wdst,2), BOFF(bdst,2), agg_cc, NC, eps + l*4 + 2, 0);
            launch_tab(T);
        }
        // EDGE4
        {
            const float* XSs[4]  = {xs_bb, xs_bc, xs_cc, xs_cb};
            float*       AGGs[4] = {agg_bb, agg_bc, agg_cc, agg_cb};
            JobTab T = {};
            for (int tt = 0; tt < 4; tt++){
                int E = in_sizes[4 + 3*tt];
                addJob(T, ea[tt], WOFF(We,tt), BOFF(be,tt), AGGs[tt], E, nullptr, FLAG_EDGE,
                       ei[tt], ewt[tt], XSs[tt]);
            }
            launch_tab(T);
        }
        // MLP1 (gelu)
        {
            JobTab T = {};
            addJob(T, agg_bb, WOFF(Wm1,0), BOFF(bm1,0), xs_bb, NB, nullptr, FLAG_GELU);
            addJob(T, agg_cb, WOFF(Wm1,3), BOFF(bm1,3), xs_bc, NB, nullptr, FLAG_GELU);
            addJob(T, agg_bc, WOFF(Wm1,1), BOFF(bm1,1), xs_cc, NC, nullptr, FLAG_GELU);
            addJob(T, agg_cc, WOFF(Wm1,2), BOFF(bm1,2), xs_cb, NC, nullptr, FLAG_GELU);
            launch_tab(T);
        }
        // MLP2
        {
            JobTab T = {};
            addJob(T, xs_bb, WOFF(Wm2,0), BOFF(bm2,0), agg_bb, NB, nullptr, 0);
            addJob(T, xs_bc, WOFF(Wm2,3), BOFF(bm2,3), agg_cb, NB, nullptr, 0);
            addJob(T, xs_cc, WOFF(Wm2,1), BOFF(bm2,1), agg_bc, NC, nullptr, 0);
            addJob(T, xs_cb, WOFF(Wm2,2), BOFF(bm2,2), agg_cc, NC, nullptr, 0);
            launch_tab(T);
        }
        // residual + gelu combine
        combine_kernel<<<(NBF+255)/256, 256>>>(xb, agg_bb, agg_cb, NBF);
        combine_kernel<<<(NCF+255)/256, 256>>>(xc, agg_bc, agg_cc, NCF);
        #undef WOFF
        #undef BOFF
    }

    float* out = (float*)d_out;
    cudaMemcpyAsync(out,       xb, sizeof(float)*(size_t)NBF, cudaMemcpyDeviceToDevice, 0);
    cudaMemcpyAsync(out + NBF, xc, sizeof(float)*(size_t)NCF, cudaMemcpyDeviceToDevice, 0);
}

// round 16
// speedup vs baseline: 1.4770x; 1.0009x over previous
#include <cuda_runtime.h>
#include <cstdint>

#define HID 128
#define NB 50000
#define NC 2500
#define NLAYERS 2
#define NBF (NB*HID)
#define NCF (NC*HID)

typedef unsigned long long u64;

#define SA_STRIDE 132
#define SMEM_BYTES ((HID*HID + 64*SA_STRIDE)*4)   // 99328 B -> 2 CTAs/SM
#define GRID_P 296

#define FLAG_GELU 1
#define FLAG_EDGE 2

// ---------- packed f32x2 helpers ----------
__device__ __forceinline__ u64 pack2(float x, float y){
    u64 d; asm("mov.b64 %0, {%1, %2};" : "=l"(d) : "f"(x), "f"(y)); return d;
}
__device__ __forceinline__ float2 unpack2(u64 d){
    float2 v; asm("mov.b64 {%0, %1}, %2;" : "=f"(v.x), "=f"(v.y) : "l"(d)); return v;
}
__device__ __forceinline__ u64 fma2(u64 a, u64 b, u64 c){
    u64 d; asm("fma.rn.f32x2 %0, %1, %2, %3;" : "=l"(d) : "l"(a), "l"(b), "l"(c)); return d;
}
// ---------- branchless erf, A&S 7.1.26 ----------
__device__ __forceinline__ float erf_apx(float z){   // z >= 0
    float den = fmaf(0.3275911f, z, 1.0f);
    float t; asm("rcp.approx.f32 %0, %1;" : "=f"(t) : "f"(den));
    float p = fmaf(1.061405429f, t, -1.453152027f);
    p = fmaf(p, t, 1.421413741f);
    p = fmaf(p, t, -0.284496736f);
    p = fmaf(p, t, 0.254829592f);
    p = p * t;
    float e = __expf(-z * z);
    return fmaf(-p, e, 1.0f);
}
__device__ __forceinline__ float gelu_f(float x){
    float z = fabsf(x) * 0.70710678118654752440f;
    float er = copysignf(erf_apx(z), x);
    return 0.5f * x * (1.0f + er);
}
__device__ __forceinline__ float gelu_w(float x, float hw){   // hw = 0.5*w
    float z = fabsf(x) * 0.70710678118654752440f;
    float er = copysignf(erf_apx(z), x);
    return hw * x * (1.0f + er);
}
__device__ __forceinline__ void red_add_v4(float* p, float a, float b, float c, float d){
    asm volatile("red.global.add.v4.f32 [%0], {%1, %2, %3, %4};"
                 :: "l"(p), "f"(a), "f"(b), "f"(c), "f"(d) : "memory");
}
__device__ __forceinline__ void prefetch_l1(const void* p){
    asm volatile("prefetch.global.L1 [%0];" :: "l"(p));
}
__device__ __forceinline__ void prefetch_l2(const void* p){
    asm volatile("prefetch.global.L2 [%0];" :: "l"(p));
}

// ---------- job table ----------
struct Job {
    const float* A; const float* W; const float* bias;
    float* out;
    const int* ei; const float* ew; const float* xs;
    const float* eps;
    int rows; int tile_ofs; int flags; int _pad;
};
struct JobTab { Job j[8]; int njobs; int total_tiles; };

// ---------- persistent multi-job fused GEMM kernel ----------
// Tile 64x128. thread t: tr=t/16 -> rows 4tr..+3, tc=t%16 -> cols {4tc..+3, 4tc+64..+67}
// Warp w's mainloop consumes only sA rows 8w..8w+7.
extern "C" __global__ void __launch_bounds__(256, 2)
mega_gemm(JobTab tab)
{
    extern __shared__ float smem[];
    float* sW = smem;                 // [k][c] 128x128, eps-scale folded
    float* sA = smem + HID*HID;       // 64 x SA_STRIDE
    int t = threadIdx.x;
    int tr = t >> 4, tc = t & 15, r0 = tr * 4;
    int w = t >> 5, l = t & 31;
    int cached = -1;

    for (int tile = blockIdx.x; tile < tab.total_tiles; tile += gridDim.x){
        int jid = 0;
        #pragma unroll
        for (int q = 1; q < 8; q++)
            if (q < tab.njobs && tile >= tab.j[q].tile_ofs) jid = q;
        const Job J = tab.j[jid];
        int row0 = (tile - J.tile_ofs) * 64;
        const bool edge = (J.flags & FLAG_EDGE) != 0;

        if (jid != cached){
            __syncthreads();          // all warps done with old sW/sA
            float scale = J.eps ? (1.0f + *J.eps) : 1.0f;
            const float4* W4 = (const float4*)J.W;
            float4* s4 = (float4*)sW;
            #pragma unroll
            for (int i = 0; i < 16; i++){
                float4 v = W4[t + 256*i];
                v.x *= scale; v.y *= scale; v.z *= scale; v.w *= scale;
                s4[t + 256*i] = v;
            }
            cached = jid;
            __syncthreads();
        }

        int4 src4 = make_int4(0,0,0,0);
        if (!edge){
            // ======== NODE staging: CTA-wide, barriered (proven at peak) ========
            __syncthreads();          // previous tile's sA reads done
            {
                const float4* A4 = (const float4*)J.A;
                float4 v[8];
                #pragma unroll
                for (int i = 0; i < 8; i++){
                    int idx = t + 256*i;
                    int r = idx >> 5, c4 = idx & 31;
                    v[i] = (row0 + r < J.rows) ? A4[(size_t)(row0 + r)*32 + c4]
                                               : make_float4(0.f,0.f,0.f,0.f);
                }
                #pragma unroll
                for (int i = 0; i < 8; i++){
                    int idx = t + 256*i;
                    int r = idx >> 5, c4 = idx & 31;
                    *reinterpret_cast<float4*>(sA + r*SA_STRIDE + 4*c4) = v[i];
                }
            }
            // prefetch next tile's A panel (1 line/thread = full 32KB)
            {
                int nrow = row0 + (int)gridDim.x*64 + (t >> 2);
                if (nrow < J.rows)
                    prefetch_l1(J.A + (size_t)nrow*HID + (t & 3)*32);
            }
            __syncthreads();
        } else {
            // ======== EDGE staging: per-warp private (rows 8w..8w+7), NO CTA barrier ====
            src4 = *reinterpret_cast<const int4*>(J.ei + row0 + r0);   // E%64==0
            if (tc < 4){   // prefetch xs gather lines early (L1: consumed this tile)
                prefetch_l1(J.xs + (size_t)src4.x*HID + tc*32);
                prefetch_l1(J.xs + (size_t)src4.y*HID + tc*32);
                prefetch_l1(J.xs + (size_t)src4.z*HID + tc*32);
                prefetch_l1(J.xs + (size_t)src4.w*HID + tc*32);
            }
            {
                const float4* A4 = (const float4*)J.A;
                int rr = 8*w + (l >> 2);           // this lane's row
                int cq = l & 3;
                const float4* gp = A4 + (size_t)(row0 + rr)*32 + cq;
                float4 v[8];
                #pragma unroll
                for (int i = 0; i < 8; i++) v[i] = gp[4*i];
                float* sp = sA + rr*SA_STRIDE + 4*cq;
                #pragma unroll
                for (int i = 0; i < 8; i++)
                    *reinterpret_cast<float4*>(sp + 16*i) = v[i];
            }
            // per-warp prefetch of next tile's own rows -> L2 (L1 has no room:
            // 34KB left after smem carveout vs 64KB/wave of prefetch traffic)
            {
                int nt0 = row0 + (int)gridDim.x*64;
                if (nt0 < J.rows)
                    prefetch_l2(J.A + (size_t)(nt0 + 8*w + (l >> 2))*HID + (l & 3)*32);
            }
            __syncwarp();
        }

        // ---- mainloop (FFMA2 peak) ----
        u64 acc[4][2][2];
        #pragma unroll
        for (int r=0;r<4;r++)
            #pragma unroll
            for (int j=0;j<2;j++){ acc[r][j][0]=0ULL; acc[r][j][1]=0ULL; }
        #pragma unroll 2
        for (int k0 = 0; k0 < HID; k0 += 4){
            float4 av[4];
            #pragma unroll
            for (int r=0;r<4;r++)
                av[r] = *reinterpret_cast<const float4*>(sA + (r0+r)*SA_STRIDE + k0);
            #pragma unroll
            for (int kk=0;kk<4;kk++){
                const float* wrow = sW + (k0+kk)*HID + 4*tc;
                ulonglong2 w0 = *reinterpret_cast<const ulonglong2*>(wrow);
                ulonglong2 w1 = *reinterpret_cast<const ulonglong2*>(wrow + 64);
                #pragma unroll
                for (int r=0;r<4;r++){
                    float a = (kk==0)?av[r].x:(kk==1)?av[r].y:(kk==2)?av[r].z:av[r].w;
                    u64 a2 = pack2(a, a);
                    acc[r][0][0] = fma2(a2, w0.x, acc[r][0][0]);
                    acc[r][0][1] = fma2(a2, w0.y, acc[r][0][1]);
                    acc[r][1][0] = fma2(a2, w1.x, acc[r][1][0]);
                    acc[r][1][1] = fma2(a2, w1.y, acc[r][1][1]);
                }
            }
        }

        // ---- fused epilogue ----
        float4 bv0 = *reinterpret_cast<const float4*>(J.bias + 4*tc);
        float4 bv1 = *reinterpret_cast<const float4*>(J.bias + 4*tc + 64);
        if (!edge){
            #pragma unroll
            for (int r=0;r<4;r++){
                int row = row0 + r0 + r;
                if (row >= J.rows) continue;
                float2 a00 = unpack2(acc[r][0][0]);
                float2 a01 = unpack2(acc[r][0][1]);
                float2 a10 = unpack2(acc[r][1][0]);
                float2 a11 = unpack2(acc[r][1][1]);
                float o0 = a00.x + bv0.x, o1 = a00.y + bv0.y;
                float o2 = a01.x + bv0.z, o3 = a01.y + bv0.w;
                float p0 = a10.x + bv1.x, p1 = a10.y + bv1.y;
                float p2 = a11.x + bv1.z, p3 = a11.y + bv1.w;
                if (J.flags & FLAG_GELU){
                    o0=gelu_f(o0); o1=gelu_f(o1); o2=gelu_f(o2); o3=gelu_f(o3);
                    p0=gelu_f(p0); p1=gelu_f(p1); p2=gelu_f(p2); p3=gelu_f(p3);
                }
                *reinterpret_cast<float4*>(J.out + (size_t)row*HID + 4*tc)      = make_float4(o0,o1,o2,o3);
                *reinterpret_cast<float4*>(J.out + (size_t)row*HID + 4*tc + 64) = make_float4(p0,p1,p2,p3);
            }
        } else {
            int4   dst4 = *reinterpret_cast<const int4*>(J.ei + J.rows + row0 + r0);
            float4 ew4  = *reinterpret_cast<const float4*>(J.ew + row0 + r0);
            int   srcs[4] = {src4.x, src4.y, src4.z, src4.w};
            int   dsts[4] = {dst4.x, dst4.y, dst4.z, dst4.w};
            float hwts[4] = {0.5f*ew4.x, 0.5f*ew4.y, 0.5f*ew4.z, 0.5f*ew4.w};
            #pragma unroll
            for (int r=0;r<4;r++){
                const float* xsr = J.xs + (size_t)srcs[r]*HID;
                float4 xv0 = *reinterpret_cast<const float4*>(xsr + 4*tc);
                float4 xv1 = *reinterpret_cast<const float4*>(xsr + 4*tc + 64);
                float2 a00 = unpack2(acc[r][0][0]);
                float2 a01 = unpack2(acc[r][0][1]);
                float2 a10 = unpack2(acc[r][1][0]);
                float2 a11 = unpack2(acc[r][1][1]);
                float hw = hwts[r];
                float m0 = gelu_w(a00.x + bv0.x + xv0.x, hw);
                float m1 = gelu_w(a00.y + bv0.y + xv0.y, hw);
                float m2 = gelu_w(a01.x + bv0.z + xv0.z, hw);
                float m3 = gelu_w(a01.y + bv0.w + xv0.w, hw);
                float n0 = gelu_w(a10.x + bv1.x + xv1.x, hw);
                float n1 = gelu_w(a10.y + bv1.y + xv1.y, hw);
                float n2 = gelu_w(a11.x + bv1.z + xv1.z, hw);
                float n3 = gelu_w(a11.y + bv1.w + xv1.w, hw);
                float* op = J.out + (size_t)dsts[r]*HID + 4*tc;
                red_add_v4(op,      m0, m1, m2, m3);
                red_add_v4(op + 64, n0, n1, n2, n3);
            }
        }
    }
}

// ---------- x += gelu(a + b) ----------
extern "C" __global__ void combine_kernel(float* __restrict__ x, const float* __restrict__ a,
                                          const float* __restrict__ b, int n){
    int i = blockIdx.x * blockDim.x + threadIdx.x;
    if (i < n) x[i] += gelu_f(a[i] + b[i]);
}

// ---------- scratch ----------
__device__ float g_buf[(size_t)5*NBF + (size_t)5*NCF];

static void addJob(JobTab& T, const float* A, const float* W, const float* b, float* out,
                   int rows, const float* eps, int flags,
                   const int* ei = nullptr, const float* ew = nullptr, const float* xs = nullptr){
    Job& J = T.j[T.njobs];
    J.A = A; J.W = W; J.bias = b; J.out = out;
    J.ei = ei; J.ew = ew; J.xs = xs; J.eps = eps;
    J.rows = rows; J.tile_ofs = T.total_tiles; J.flags = flags; J._pad = 0;
    T.total_tiles += (rows + 63) / 64;
    T.njobs++;
}
static void launch_tab(const JobTab& T){
    int G = T.total_tiles < GRID_P ? T.total_tiles : GRID_P;
    mega_gemm<<<G, 256, SMEM_BYTES>>>(T);
}

extern "C" void kernel_launch(void* const* d_in, const int* in_sizes, int n_in,
                              void* d_out, int out_size)
{
    (void)n_in; (void)out_size;
    const float* x_base = (const float*)d_in[0];
    const float* x_cent = (const float*)d_in[1];
    const int*   ei[4]  = {(const int*)d_in[2], (const int*)d_in[5], (const int*)d_in[8],  (const int*)d_in[11]};
    const float* ea[4]  = {(const float*)d_in[3], (const float*)d_in[6], (const float*)d_in[9],  (const float*)d_in[12]};
    const float* ewt[4] = {(const float*)d_in[4], (const float*)d_in[7], (const float*)d_in[10], (const float*)d_in[13]};
    const float* Wsrc = (const float*)d_in[14];
    const float* bsrc = (const float*)d_in[15];
    const float* Wdst = (const float*)d_in[16];
    const float* bdst = (const float*)d_in[17];
    const float* eps  = (const float*)d_in[18];
    const float* We   = (const float*)d_in[19];
    const float* be   = (const float*)d_in[20];
    const float* Wm1  = (const float*)d_in[21];
    const float* bm1  = (const float*)d_in[22];
    const float* Wm2  = (const float*)d_in[23];
    const float* bm2  = (const float*)d_in[24];

    float* base = nullptr;
    cudaGetSymbolAddress((void**)&base, g_buf);
    float* xb     = base;
    float* xs_bb  = base + (size_t)1*NBF;
    float* xs_bc  = base + (size_t)2*NBF;
    float* agg_bb = base + (size_t)3*NBF;
    float* agg_cb = base + (size_t)4*NBF;
    float* xc     = base + (size_t)5*NBF;
    float* xs_cc  = xc + (size_t)1*NCF;
    float* xs_cb  = xc + (size_t)2*NCF;
    float* agg_bc = xc + (size_t)3*NCF;
    float* agg_cc = xc + (size_t)4*NCF;

    cudaFuncSetAttribute((const void*)mega_gemm, cudaFuncAttributeMaxDynamicSharedMemorySize, SMEM_BYTES);

    cudaMemcpyAsync(xb, x_base, sizeof(float)*(size_t)NBF, cudaMemcpyDeviceToDevice, 0);
    cudaMemcpyAsync(xc, x_cent, sizeof(float)*(size_t)NCF, cudaMemcpyDeviceToDevice, 0);

    for (int l = 0; l < NLAYERS; l++){
        #define WOFF(P,t) ((P) + ((size_t)l*4 + (t))*HID*HID)
        #define BOFF(P,t) ((P) + ((size_t)l*4 + (t))*HID)
        // NODE8: 4x lin_src + 4x lin_dst
        {
            JobTab T = {};
            addJob(T, xb, WOFF(Wsrc,0), BOFF(bsrc,0), xs_bb, NB, nullptr, 0);
            addJob(T, xb, WOFF(Wsrc,1), BOFF(bsrc,1), xs_bc, NB, nullptr, 0);
            addJob(T, xc, WOFF(Wsrc,2), BOFF(bsrc,2), xs_cc, NC, nullptr, 0);
            addJob(T, xc, WOFF(Wsrc,3), BOFF(bsrc,3), xs_cb, NC, nullptr, 0);
            addJob(T, xb, WOFF(Wdst,0), BOFF(bdst,0), agg_bb, NB, eps + l*4 + 0, 0);
            addJob(T, xb, WOFF(Wdst,3), BOFF(bdst,3), agg_cb, NB, eps + l*4 + 3, 0);
            addJob(T, xc, WOFF(Wdst,1), BOFF(bdst,1), agg_bc, NC, eps + l*4 + 1, 0);
            addJob(T, xc, WOFF(Wdst,2), BOFF(bdst,2), agg_cc, NC, eps + l*4 + 2, 0);
            launch_tab(T);
        }
        // EDGE4
        {
            const float* XSs[4]  = {xs_bb, xs_bc, xs_cc, xs_cb};
            float*       AGGs[4] = {agg_bb, agg_bc, agg_cc, agg_cb};
            JobTab T = {};
            for (int tt = 0; tt < 4; tt++){
                int E = in_sizes[4 + 3*tt];
                addJob(T, ea[tt], WOFF(We,tt), BOFF(be,tt), AGGs[tt], E, nullptr, FLAG_EDGE,
                       ei[tt], ewt[tt], XSs[tt]);
            }
            launch_tab(T);
        }
        // MLP1 (gelu)
        {
            JobTab T = {};
            addJob(T, agg_bb, WOFF(Wm1,0), BOFF(bm1,0), xs_bb, NB, nullptr, FLAG_GELU);
            addJob(T, agg_cb, WOFF(Wm1,3), BOFF(bm1,3), xs_bc, NB, nullptr, FLAG_GELU);
            addJob(T, agg_bc, WOFF(Wm1,1), BOFF(bm1,1), xs_cc, NC, nullptr, FLAG_GELU);
            addJob(T, agg_cc, WOFF(Wm1,2), BOFF(bm1,2), xs_cb, NC, nullptr, FLAG_GELU);
            launch_tab(T);
        }
        // MLP2
        {
            JobTab T = {};
            addJob(T, xs_bb, WOFF(Wm2,0), BOFF(bm2,0), agg_bb, NB, nullptr, 0);
            addJob(T, xs_bc, WOFF(Wm2,3), BOFF(bm2,3), agg_cb, NB, nullptr, 0);
            addJob(T, xs_cc, WOFF(Wm2,1), BOFF(bm2,1), agg_bc, NC, nullptr, 0);
            addJob(T, xs_cb, WOFF(Wm2,2), BOFF(bm2,2), agg_cc, NC, nullptr, 0);
            launch_tab(T);
        }
        // residual + gelu combine
        combine_kernel<<<(NBF+255)/256, 256>>>(xb, agg_bb, agg_cb, NBF);
        combine_kernel<<<(NCF+255)/256, 256>>>(xc, agg_bc, agg_cc, NCF);
        #undef WOFF
        #undef BOFF
    }

    float* out = (float*)d_out;
    cudaMemcpyAsync(out,       xb, sizeof(float)*(size_t)NBF, cudaMemcpyDeviceToDevice, 0);
    cudaMemcpyAsync(out + NBF, xc, sizeof(float)*(size_t)NCF, cudaMemcpyDeviceToDevice, 0);
}

// round 17
// speedup vs baseline: 1.4936x; 1.0112x over previous
#include <cuda_runtime.h>
#include <cstdint>

#define HID 128
#define NB 50000
#define NC 2500
#define NLAYERS 2
#define NBF (NB*HID)
#define NCF (NC*HID)

typedef unsigned long long u64;

#define SA_STRIDE 132
#define SMEM_BYTES ((HID*HID + 64*SA_STRIDE)*4)   // 99328 B -> 2 CTAs/SM
#define GRID_P 296

#define FLAG_GELU 1
#define FLAG_EDGE 2

// ---------- packed f32x2 helpers ----------
__device__ __forceinline__ u64 pack2(float x, float y){
    u64 d; asm("mov.b64 %0, {%1, %2};" : "=l"(d) : "f"(x), "f"(y)); return d;
}
__device__ __forceinline__ float2 unpack2(u64 d){
    float2 v; asm("mov.b64 {%0, %1}, %2;" : "=f"(v.x), "=f"(v.y) : "l"(d)); return v;
}
__device__ __forceinline__ u64 fma2(u64 a, u64 b, u64 c){
    u64 d; asm("fma.rn.f32x2 %0, %1, %2, %3;" : "=l"(d) : "l"(a), "l"(b), "l"(c)); return d;
}
// ---------- branchless erf, A&S 7.1.26 ----------
__device__ __forceinline__ float erf_apx(float z){   // z >= 0
    float den = fmaf(0.3275911f, z, 1.0f);
    float t; asm("rcp.approx.f32 %0, %1;" : "=f"(t) : "f"(den));
    float p = fmaf(1.061405429f, t, -1.453152027f);
    p = fmaf(p, t, 1.421413741f);
    p = fmaf(p, t, -0.284496736f);
    p = fmaf(p, t, 0.254829592f);
    p = p * t;
    float e = __expf(-z * z);
    return fmaf(-p, e, 1.0f);
}
__device__ __forceinline__ float gelu_f(float x){
    float z = fabsf(x) * 0.70710678118654752440f;
    float er = copysignf(erf_apx(z), x);
    return 0.5f * x * (1.0f + er);
}
__device__ __forceinline__ float gelu_w(float x, float hw){   // hw = 0.5*w
    float z = fabsf(x) * 0.70710678118654752440f;
    float er = copysignf(erf_apx(z), x);
    return hw * x * (1.0f + er);
}
__device__ __forceinline__ void red_add_v4(float* p, float a, float b, float c, float d){
    asm volatile("red.global.add.v4.f32 [%0], {%1, %2, %3, %4};"
                 :: "l"(p), "f"(a), "f"(b), "f"(c), "f"(d) : "memory");
}
__device__ __forceinline__ void prefetch_l1(const void* p){
    asm volatile("prefetch.global.L1 [%0];" :: "l"(p));
}
__device__ __forceinline__ void prefetch_l2(const void* p){
    asm volatile("prefetch.global.L2 [%0];" :: "l"(p));
}

// ---------- job table ----------
struct Job {
    const float* A; const float* W; const float* bias;
    float* out;
    const int* ei; const float* ew; const float* xs;
    const float* eps;
    int rows; int tile_ofs; int flags; int _pad;
};
struct JobTab { Job j[8]; int njobs; int total_tiles; };

// ---------- persistent multi-job fused GEMM kernel ----------
// Tile 64x128. thread t: tr=t/16 -> rows 4tr..+3, tc=t%16 -> cols {4tc..+3, 4tc+64..+67}
// Warp w's mainloop consumes only sA rows 8w..8w+7.
extern "C" __global__ void __launch_bounds__(256, 2)
mega_gemm(JobTab tab)
{
    extern __shared__ float smem[];
    float* sW = smem;                 // [k][c] 128x128, eps-scale folded
    float* sA = smem + HID*HID;       // 64 x SA_STRIDE
    int t = threadIdx.x;
    int tr = t >> 4, tc = t & 15, r0 = tr * 4;
    int w = t >> 5, l = t & 31;
    int cached = -1;

    for (int tile = blockIdx.x; tile < tab.total_tiles; tile += gridDim.x){
        int jid = 0;
        #pragma unroll
        for (int q = 1; q < 8; q++)
            if (q < tab.njobs && tile >= tab.j[q].tile_ofs) jid = q;
        const Job J = tab.j[jid];
        int row0 = (tile - J.tile_ofs) * 64;
        const bool edge = (J.flags & FLAG_EDGE) != 0;

        if (jid != cached){
            __syncthreads();          // all warps done with old sW/sA
            float scale = J.eps ? (1.0f + *J.eps) : 1.0f;
            const float4* W4 = (const float4*)J.W;
            float4* s4 = (float4*)sW;
            #pragma unroll
            for (int i = 0; i < 16; i++){
                float4 v = W4[t + 256*i];
                v.x *= scale; v.y *= scale; v.z *= scale; v.w *= scale;
                s4[t + 256*i] = v;
            }
            cached = jid;
            __syncthreads();
        }

        int4 src4 = make_int4(0,0,0,0);
        if (!edge){
            // ======== NODE staging: CTA-wide, barriered (proven at peak) ========
            __syncthreads();          // previous tile's sA reads done
            {
                const float4* A4 = (const float4*)J.A;
                float4 v[8];
                #pragma unroll
                for (int i = 0; i < 8; i++){
                    int idx = t + 256*i;
                    int r = idx >> 5, c4 = idx & 31;
                    v[i] = (row0 + r < J.rows) ? A4[(size_t)(row0 + r)*32 + c4]
                                               : make_float4(0.f,0.f,0.f,0.f);
                }
                #pragma unroll
                for (int i = 0; i < 8; i++){
                    int idx = t + 256*i;
                    int r = idx >> 5, c4 = idx & 31;
                    *reinterpret_cast<float4*>(sA + r*SA_STRIDE + 4*c4) = v[i];
                }
            }
            // prefetch next tile's A panel (1 line/thread = full 32KB)
            {
                int nrow = row0 + (int)gridDim.x*64 + (t >> 2);
                if (nrow < J.rows)
                    prefetch_l1(J.A + (size_t)nrow*HID + (t & 3)*32);
            }
            __syncthreads();
        } else {
            // ======== EDGE staging: per-warp private (rows 8w..8w+7), NO CTA barrier ====
            src4 = *reinterpret_cast<const int4*>(J.ei + row0 + r0);   // E%64==0
            if (tc < 4){   // prefetch xs gather lines early (L1: consumed this tile)
                prefetch_l1(J.xs + (size_t)src4.x*HID + tc*32);
                prefetch_l1(J.xs + (size_t)src4.y*HID + tc*32);
                prefetch_l1(J.xs + (size_t)src4.z*HID + tc*32);
                prefetch_l1(J.xs + (size_t)src4.w*HID + tc*32);
            }
            {
                const float4* A4 = (const float4*)J.A;
                int rr = 8*w + (l >> 2);           // this lane's row
                int cq = l & 3;
                const float4* gp = A4 + (size_t)(row0 + rr)*32 + cq;
                float4 v[8];
                #pragma unroll
                for (int i = 0; i < 8; i++) v[i] = gp[4*i];
                float* sp = sA + rr*SA_STRIDE + 4*cq;
                #pragma unroll
                for (int i = 0; i < 8; i++)
                    *reinterpret_cast<float4*>(sp + 16*i) = v[i];
            }
            // per-warp prefetch of next tile's own rows -> L2
            {
                int nt0 = row0 + (int)gridDim.x*64;
                if (nt0 < J.rows)
                    prefetch_l2(J.A + (size_t)(nt0 + 8*w + (l >> 2))*HID + (l & 3)*32);
            }
            __syncwarp();
        }

        // ---- mainloop (FFMA2 peak) ----
        u64 acc[4][2][2];
        #pragma unroll
        for (int r=0;r<4;r++)
            #pragma unroll
            for (int j=0;j<2;j++){ acc[r][j][0]=0ULL; acc[r][j][1]=0ULL; }
        #pragma unroll 2
        for (int k0 = 0; k0 < HID; k0 += 4){
            float4 av[4];
            #pragma unroll
            for (int r=0;r<4;r++)
                av[r] = *reinterpret_cast<const float4*>(sA + (r0+r)*SA_STRIDE + k0);
            #pragma unroll
            for (int kk=0;kk<4;kk++){
                const float* wrow = sW + (k0+kk)*HID + 4*tc;
                ulonglong2 w0 = *reinterpret_cast<const ulonglong2*>(wrow);
                ulonglong2 w1 = *reinterpret_cast<const ulonglong2*>(wrow + 64);
                #pragma unroll
                for (int r=0;r<4;r++){
                    float a = (kk==0)?av[r].x:(kk==1)?av[r].y:(kk==2)?av[r].z:av[r].w;
                    u64 a2 = pack2(a, a);
                    acc[r][0][0] = fma2(a2, w0.x, acc[r][0][0]);
                    acc[r][0][1] = fma2(a2, w0.y, acc[r][0][1]);
                    acc[r][1][0] = fma2(a2, w1.x, acc[r][1][0]);
                    acc[r][1][1] = fma2(a2, w1.y, acc[r][1][1]);
                }
            }
        }

        // ---- fused epilogue ----
        float4 bv0 = *reinterpret_cast<const float4*>(J.bias + 4*tc);
        float4 bv1 = *reinterpret_cast<const float4*>(J.bias + 4*tc + 64);
        if (!edge){
            #pragma unroll
            for (int r=0;r<4;r++){
                int row = row0 + r0 + r;
                if (row >= J.rows) continue;
                float2 a00 = unpack2(acc[r][0][0]);
                float2 a01 = unpack2(acc[r][0][1]);
                float2 a10 = unpack2(acc[r][1][0]);
                float2 a11 = unpack2(acc[r][1][1]);
                float o0 = a00.x + bv0.x, o1 = a00.y + bv0.y;
                float o2 = a01.x + bv0.z, o3 = a01.y + bv0.w;
                float p0 = a10.x + bv1.x, p1 = a10.y + bv1.y;
                float p2 = a11.x + bv1.z, p3 = a11.y + bv1.w;
                if (J.flags & FLAG_GELU){
                    o0=gelu_f(o0); o1=gelu_f(o1); o2=gelu_f(o2); o3=gelu_f(o3);
                    p0=gelu_f(p0); p1=gelu_f(p1); p2=gelu_f(p2); p3=gelu_f(p3);
                }
                *reinterpret_cast<float4*>(J.out + (size_t)row*HID + 4*tc)      = make_float4(o0,o1,o2,o3);
                *reinterpret_cast<float4*>(J.out + (size_t)row*HID + 4*tc + 64) = make_float4(p0,p1,p2,p3);
            }
        } else {
            int4   dst4 = *reinterpret_cast<const int4*>(J.ei + J.rows + row0 + r0);
            float4 ew4  = *reinterpret_cast<const float4*>(J.ew + row0 + r0);
            int   srcs[4] = {src4.x, src4.y, src4.z, src4.w};
            int   dsts[4] = {dst4.x, dst4.y, dst4.z, dst4.w};
            float hwts[4] = {0.5f*ew4.x, 0.5f*ew4.y, 0.5f*ew4.z, 0.5f*ew4.w};
            #pragma unroll
            for (int r=0;r<4;r++){
                const float* xsr = J.xs + (size_t)srcs[r]*HID;
                float4 xv0 = *reinterpret_cast<const float4*>(xsr + 4*tc);
                float4 xv1 = *reinterpret_cast<const float4*>(xsr + 4*tc + 64);
                float2 a00 = unpack2(acc[r][0][0]);
                float2 a01 = unpack2(acc[r][0][1]);
                float2 a10 = unpack2(acc[r][1][0]);
                float2 a11 = unpack2(acc[r][1][1]);
                float hw = hwts[r];
                float m0 = gelu_w(a00.x + bv0.x + xv0.x, hw);
                float m1 = gelu_w(a00.y + bv0.y + xv0.y, hw);
                float m2 = gelu_w(a01.x + bv0.z + xv0.z, hw);
                float m3 = gelu_w(a01.y + bv0.w + xv0.w, hw);
                float n0 = gelu_w(a10.x + bv1.x + xv1.x, hw);
                float n1 = gelu_w(a10.y + bv1.y + xv1.y, hw);
                float n2 = gelu_w(a11.x + bv1.z + xv1.z, hw);
                float n3 = gelu_w(a11.y + bv1.w + xv1.w, hw);
                float* op = J.out + (size_t)dsts[r]*HID + 4*tc;
                red_add_v4(op,      m0, m1, m2, m3);
                red_add_v4(op + 64, n0, n1, n2, n3);
            }
        }
    }
}

// ---------- xout = xin + gelu(a + b), vectorized ----------
extern "C" __global__ void combine_kernel(float* __restrict__ xout, const float* __restrict__ xin,
                                          const float* __restrict__ a, const float* __restrict__ b,
                                          int n4){
    int i = blockIdx.x * blockDim.x + threadIdx.x;
    if (i < n4){
        float4 xi = ((const float4*)xin)[i];
        float4 av = ((const float4*)a)[i];
        float4 bv = ((const float4*)b)[i];
        float4 o;
        o.x = xi.x + gelu_f(av.x + bv.x);
        o.y = xi.y + gelu_f(av.y + bv.y);
        o.z = xi.z + gelu_f(av.z + bv.z);
        o.w = xi.w + gelu_f(av.w + bv.w);
        ((float4*)xout)[i] = o;
    }
}

// ---------- scratch ----------
__device__ float g_buf[(size_t)5*NBF + (size_t)5*NCF];

static void addJob(JobTab& T, const float* A, const float* W, const float* b, float* out,
                   int rows, const float* eps, int flags,
                   const int* ei = nullptr, const float* ew = nullptr, const float* xs = nullptr){
    Job& J = T.j[T.njobs];
    J.A = A; J.W = W; J.bias = b; J.out = out;
    J.ei = ei; J.ew = ew; J.xs = xs; J.eps = eps;
    J.rows = rows; J.tile_ofs = T.total_tiles; J.flags = flags; J._pad = 0;
    T.total_tiles += (rows + 63) / 64;
    T.njobs++;
}
static void launch_tab(const JobTab& T){
    int G = T.total_tiles < GRID_P ? T.total_tiles : GRID_P;
    mega_gemm<<<G, 256, SMEM_BYTES>>>(T);
}

extern "C" void kernel_launch(void* const* d_in, const int* in_sizes, int n_in,
                              void* d_out, int out_size)
{
    (void)n_in; (void)out_size;
    const float* x_base = (const float*)d_in[0];
    const float* x_cent = (const float*)d_in[1];
    const int*   ei[4]  = {(const int*)d_in[2], (const int*)d_in[5], (const int*)d_in[8],  (const int*)d_in[11]};
    const float* ea[4]  = {(const float*)d_in[3], (const float*)d_in[6], (const float*)d_in[9],  (const float*)d_in[12]};
    const float* ewt[4] = {(const float*)d_in[4], (const float*)d_in[7], (const float*)d_in[10], (const float*)d_in[13]};
    const float* Wsrc = (const float*)d_in[14];
    const float* bsrc = (const float*)d_in[15];
    const float* Wdst = (const float*)d_in[16];
    const float* bdst = (const float*)d_in[17];
    const float* eps  = (const float*)d_in[18];
    const float* We   = (const float*)d_in[19];
    const float* be   = (const float*)d_in[20];
    const float* Wm1  = (const float*)d_in[21];
    const float* bm1  = (const float*)d_in[22];
    const float* Wm2  = (const float*)d_in[23];
    const float* bm2  = (const float*)d_in[24];

    float* base = nullptr;
    cudaGetSymbolAddress((void**)&base, g_buf);
    float* xb     = base;
    float* xs_bb  = base + (size_t)1*NBF;
    float* xs_bc  = base + (size_t)2*NBF;
    float* agg_bb = base + (size_t)3*NBF;
    float* agg_cb = base + (size_t)4*NBF;
    float* xc     = base + (size_t)5*NBF;
    float* xs_cc  = xc + (size_t)1*NCF;
    float* xs_cb  = xc + (size_t)2*NCF;
    float* agg_bc = xc + (size_t)3*NCF;
    float* agg_cc = xc + (size_t)4*NCF;
    float* out    = (float*)d_out;

    cudaFuncSetAttribute((const void*)mega_gemm, cudaFuncAttributeMaxDynamicSharedMemorySize, SMEM_BYTES);

    for (int l = 0; l < NLAYERS; l++){
        #define WOFF(P,t) ((P) + ((size_t)l*4 + (t))*HID*HID)
        #define BOFF(P,t) ((P) + ((size_t)l*4 + (t))*HID)
        // layer inputs: first layer reads harness buffers directly (no copy)
        const float* xbi = (l == 0) ? x_base : xb;
        const float* xci = (l == 0) ? x_cent : xc;
        // layer outputs: final layer's combine writes straight into d_out
        float* xbo = (l == NLAYERS-1) ? out        : xb;
        float* xco = (l == NLAYERS-1) ? out + NBF  : xc;

        // NODE8: 4x lin_src + 4x lin_dst
        {
            JobTab T = {};
            addJob(T, xbi, WOFF(Wsrc,0), BOFF(bsrc,0), xs_bb, NB, nullptr, 0);
            addJob(T, xbi, WOFF(Wsrc,1), BOFF(bsrc,1), xs_bc, NB, nullptr, 0);
            addJob(T, xci, WOFF(Wsrc,2), BOFF(bsrc,2), xs_cc, NC, nullptr, 0);
            addJob(T, xci, WOFF(Wsrc,3), BOFF(bsrc,3), xs_cb, NC, nullptr, 0);
            addJob(T, xbi, WOFF(Wdst,0), BOFF(bdst,0), agg_bb, NB, eps + l*4 + 0, 0);
            addJob(T, xbi, WOFF(Wdst,3), BOFF(bdst,3), agg_cb, NB, eps + l*4 + 3, 0);
            addJob(T, xci, WOFF(Wdst,1), BOFF(bdst,1), agg_bc, NC, eps + l*4 + 1, 0);
            addJob(T, xci, WOFF(Wdst,2), BOFF(bdst,2), agg_cc, NC, eps + l*4 + 2, 0);
            launch_tab(T);
        }
        // EDGE4
        {
            const float* XSs[4]  = {xs_bb, xs_bc, xs_cc, xs_cb};
            float*       AGGs[4] = {agg_bb, agg_bc, agg_cc, agg_cb};
            JobTab T = {};
            for (int tt = 0; tt < 4; tt++){
                int E = in_sizes[4 + 3*tt];
                addJob(T, ea[tt], WOFF(We,tt), BOFF(be,tt), AGGs[tt], E, nullptr, FLAG_EDGE,
                       ei[tt], ewt[tt], XSs[tt]);
            }
            launch_tab(T);
        }
        // MLP1 (gelu)
        {
            JobTab T = {};
            addJob(T, agg_bb, WOFF(Wm1,0), BOFF(bm1,0), xs_bb, NB, nullptr, FLAG_GELU);
            addJob(T, agg_cb, WOFF(Wm1,3), BOFF(bm1,3), xs_bc, NB, nullptr, FLAG_GELU);
            addJob(T, agg_bc, WOFF(Wm1,1), BOFF(bm1,1), xs_cc, NC, nullptr, FLAG_GELU);
            addJob(T, agg_cc, WOFF(Wm1,2), BOFF(bm1,2), xs_cb, NC, nullptr, FLAG_GELU);
            launch_tab(T);
        }
        // MLP2
        {
            JobTab T = {};
            addJob(T, xs_bb, WOFF(Wm2,0), BOFF(bm2,0), agg_bb, NB, nullptr, 0);
            addJob(T, xs_bc, WOFF(Wm2,3), BOFF(bm2,3), agg_cb, NB, nullptr, 0);
            addJob(T, xs_cc, WOFF(Wm2,1), BOFF(bm2,1), agg_bc, NC, nullptr, 0);
            addJob(T, xs_cb, WOFF(Wm2,2), BOFF(bm2,2), agg_cc, NC, nullptr, 0);
            launch_tab(T);
        }
        // residual + gelu combine (reads layer input, writes layer output)
        combine_kernel<<<(NBF/4+255)/256, 256>>>(xbo, xbi, agg_bb, agg_cb, NBF/4);
        combine_kernel<<<(NCF/4+255)/256, 256>>>(xco, xci, agg_bc, agg_cc, NCF/4);
        #undef WOFF
        #undef BOFF
    }
}